// round 9
// baseline (speedup 1.0000x reference)
#include <cuda_runtime.h>
#include <cuda_fp16.h>
#include <cstdint>

#define Bq    8
#define CIN   128
#define COUT  128
#define HH    256
#define WW    256
#define SDIM  512

#define PXW   20            // words per tile row in a k-plane (16 cp + 4 pad)
#define KPL   (64 * PXW)    // 1280 words per k-plane (64 tiles)

__device__ float  g_style[Bq * CIN];
__device__ float  g_demod[Bq * COUT];
__device__ float  g_W2[COUT * CIN];
__device__ __half g_wA[48 * 4096];   // 48 steps (12 groups x 4 k) x 4096 halves, fragment-ordered U

#define MMA_F16(d, a, bb)                                                 \
    asm volatile("mma.sync.aligned.m16n8k16.row.col.f32.f16.f16.f32 "     \
                 "{%0,%1,%2,%3}, {%4,%5,%6,%7}, {%8,%9}, {%0,%1,%2,%3};"  \
                 : "+f"((d)[0]), "+f"((d)[1]), "+f"((d)[2]), "+f"((d)[3]) \
                 : "r"((a)[0]), "r"((a)[1]), "r"((a)[2]), "r"((a)[3]),    \
                   "r"((bb)[0]), "r"((bb)[1]))

// ---------------------------------------------------------------------------
// prep1: blocks 0..127 style GEMV (warp per (b,o)); blocks 128..191 W2
// ---------------------------------------------------------------------------
__global__ void prep1(const float* __restrict__ w,
                      const float* __restrict__ style_W,
                      const float* __restrict__ style_b,
                      const float* __restrict__ weight) {
    if (blockIdx.x < 128) {
        const int gw   = blockIdx.x * 8 + (threadIdx.x >> 5);
        const int lane = threadIdx.x & 31;
        const int b = gw >> 7, o = gw & 127;
        const float4* wv = (const float4*)(w + (size_t)b * SDIM);
        const float4* Wv = (const float4*)(style_W + (size_t)o * SDIM);
        float acc = 0.f;
        #pragma unroll
        for (int k = 0; k < 4; k++) {
            float4 a = wv[lane + k * 32], c = Wv[lane + k * 32];
            acc += a.x * c.x + a.y * c.y + a.z * c.z + a.w * c.w;
        }
        #pragma unroll
        for (int d = 16; d > 0; d >>= 1)
            acc += __shfl_xor_sync(0xffffffffu, acc, d);
        if (lane == 0) g_style[b * CIN + o] = acc + style_b[o];
    } else {
        int idx = (blockIdx.x - 128) * 256 + threadIdx.x;
        const float* p = weight + (size_t)idx * 9;
        float s = 0.f;
        #pragma unroll
        for (int t = 0; t < 9; t++) { float v = p[t]; s += v * v; }
        g_W2[idx] = s;
    }
}

// ---------------------------------------------------------------------------
// prep2: blocks 0..767 = Winograd-U prepack (fragment order); 768..895 = demod
//   step s = g*4 + k, g = (dy, chunk32); per-s layout identical to proven R6-R8
//   A-fragment mapping; value = U_k(w0,w1,w2).
// ---------------------------------------------------------------------------
__global__ void prep2(const float* __restrict__ weight) {
    if (blockIdx.x < 768) {
        int idx  = blockIdx.x * 256 + threadIdx.x;     // < 196608 = 48*4096
        int h    = idx & 1;
        int j    = (idx >> 1) & 3;
        int lane = (idx >> 3) & 31;
        int mt   = (idx >> 8) & 7;
        int kk   = (idx >> 11) & 1;
        int s    = idx >> 12;                          // 0..47
        int k    = s & 3;
        int g    = s >> 2;                             // 0..11
        int dy = g >> 2, chunk = g & 3;
        int m  = mt * 16 + (lane >> 2) + 8 * (j & 1);
        int kl = kk * 16 + (lane & 3) * 2 + 8 * (j >> 1) + h;
        int c  = chunk * 32 + kl;
        const float* wp = weight + ((size_t)m * CIN + c) * 9 + dy * 3;
        float w0 = wp[0], w1 = wp[1], w2 = wp[2];
        float u = (k == 0) ? w0
                : (k == 1) ? 0.5f * (w0 + w1 + w2)
                : (k == 2) ? 0.5f * (w0 - w1 + w2)
                : w2;
        g_wA[idx] = __float2half_rn(u);
    } else {
        int gw   = (blockIdx.x - 768) * 8 + (threadIdx.x >> 5);
        int lane = threadIdx.x & 31;
        int b = gw >> 7, o = gw & 127;
        float sum = 0.f;
        #pragma unroll
        for (int j = 0; j < 4; j++) {
            int i = lane + j * 32;
            float s = g_style[b * CIN + i];
            sum += s * s * g_W2[o * CIN + i];
        }
        #pragma unroll
        for (int d = 16; d > 0; d >>= 1)
            sum += __shfl_xor_sync(0xffffffffu, sum, d);
        if (lane == 0) g_demod[b * COUT + o] = rsqrtf(sum + 1e-8f);
    }
}

// ---------------------------------------------------------------------------
// main conv: CTA = (xhalf, y, b): 128 oc x 64 tiles (128 px), Winograd F(2,3)-x.
// 16 warps = 4(wm: 32oc) x 4(wn: 16 tiles); acc[2m][4k][2n][4] = 64 regs.
// ---------------------------------------------------------------------------
__global__ __launch_bounds__(512, 1)
void conv_mma_kernel(const float* __restrict__ x,
                     const float* __restrict__ bias,
                     float* __restrict__ out) {
    __shared__ float    styl[CIN];
    __shared__ uint32_t stage[2][4 * KPL];   // [buf][k][tile][cp]

    const int tid  = threadIdx.x;
    const int lane = tid & 31;
    const int warp = tid >> 5;
    const int wm   = warp >> 2;      // 0..3
    const int wn   = warp & 3;       // 0..3
    const int xh   = blockIdx.x;
    const int y    = blockIdx.y;
    const int b    = blockIdx.z;
    const int x0   = xh * 128;       // first output px of CTA

    const int gid = lane >> 2;       // 0..7
    const int tig = lane & 3;        // 0..3

    if (tid < CIN) styl[tid] = g_style[b * CIN + tid];
    __syncthreads();

    float acc[2][4][2][4];
    #pragma unroll
    for (int m = 0; m < 2; m++)
        #pragma unroll
        for (int k = 0; k < 4; k++)
            #pragma unroll
            for (int n = 0; n < 2; n++)
                #pragma unroll
                for (int j = 0; j < 4; j++) acc[m][k][n][j] = 0.f;

    // fill mapping: item = (tile, cp); thread does 2 items (i=0,1)
    const int ftile = (tid >> 2) & 63;          // warp: 8 consecutive tiles
    const int frep  = (tid >> 2) >> 6;          // 0..1
    const int fc    = tid & 3;

    // ---- fill: load 4-wide x window per tile, F(2,3) transform, store V ----
    auto fill = [&](int g, uint32_t* buf) {
        const int dy = g >> 2, chunk = g & 3;
        const int yr = y + dy - 1;
        const bool yok = (unsigned)yr < (unsigned)HH;
        const int c0 = chunk * 32;
        const int gx = x0 + 2 * ftile - 1;      // d0 position
        #pragma unroll
        for (int i = 0; i < 2; i++) {
            const int cp  = fc + 4 * (frep * 2 + i);
            const int ch0 = c0 + 2 * cp;
            const float sA = styl[ch0], sB = styl[ch0 + 1];
            const float* pA = x + (((size_t)b * CIN + ch0) * HH + yr) * WW;
            const float* pB = pA + (size_t)HH * WW;
            float d0a = 0.f, d1a = 0.f, d2a = 0.f, d3a = 0.f;
            float d0b = 0.f, d1b = 0.f, d2b = 0.f, d3b = 0.f;
            if (yok) {
                float2 mA = *(const float2*)(pA + gx + 1);
                float2 mB = *(const float2*)(pB + gx + 1);
                d1a = mA.x; d2a = mA.y; d1b = mB.x; d2b = mB.y;
                if (gx >= 0)      { d0a = pA[gx];     d0b = pB[gx]; }
                if (gx + 3 < WW)  { d3a = pA[gx + 3]; d3b = pB[gx + 3]; }
            }
            d0a *= sA; d1a *= sA; d2a *= sA; d3a *= sA;
            d0b *= sB; d1b *= sB; d2b *= sB; d3b *= sB;
            const uint32_t base = (uint32_t)(ftile * PXW + cp);
            __half2 h0 = __floats2half2_rn(d0a - d2a, d0b - d2b);
            __half2 h1 = __floats2half2_rn(d1a + d2a, d1b + d2b);
            __half2 h2 = __floats2half2_rn(d2a - d1a, d2b - d1b);
            __half2 h3 = __floats2half2_rn(d1a - d3a, d1b - d3b);
            buf[0 * KPL + base] = *(uint32_t*)&h0;
            buf[1 * KPL + base] = *(uint32_t*)&h1;
            buf[2 * KPL + base] = *(uint32_t*)&h2;
            buf[3 * KPL + base] = *(uint32_t*)&h3;
        }
    };

    // ---- compute one k-plane of group g: 2kk x (2 A-frags, 2 B-frags, 4 MMA)
    auto compute_k = [&](const uint32_t* stg, int g, int k) {
        #pragma unroll
        for (int kk = 0; kk < 2; kk++) {
            const uint4* As = ((const uint4*)g_wA) +
                              ((((size_t)(g * 4 + k) * 2 + kk) * 8 + wm * 2) * 32 + lane);
            uint4 a0 = __ldg(As);
            uint4 a1 = __ldg(As + 32);
            uint32_t bb[2][2];
            #pragma unroll
            for (int n = 0; n < 2; n++) {
                const uint32_t* p = stg + k * KPL +
                                    (wn * 16 + n * 8 + gid) * PXW + kk * 8 + tig;
                bb[n][0] = p[0];
                bb[n][1] = p[4];
            }
            MMA_F16(acc[0][k][0], (const uint32_t*)&a0, bb[0]);
            MMA_F16(acc[0][k][1], (const uint32_t*)&a0, bb[1]);
            MMA_F16(acc[1][k][0], (const uint32_t*)&a1, bb[0]);
            MMA_F16(acc[1][k][1], (const uint32_t*)&a1, bb[1]);
        }
    };

    fill(0, stage[0]);
    __syncthreads();

    #pragma unroll 1
    for (int g = 0; g < 12; g++) {
        const int cur = g & 1;
        compute_k(stage[cur], g, 0);
        if (g < 11) fill(g + 1, stage[cur ^ 1]);   // LDG covered by k=1..3 compute
        compute_k(stage[cur], g, 1);
        compute_k(stage[cur], g, 2);
        compute_k(stage[cur], g, 3);
        __syncthreads();
    }

    // ---- epilogue: inverse transform (fp32) + demod + bias, float4 stores ----
    #pragma unroll
    for (int m = 0; m < 2; m++) {
        const int oc0 = wm * 32 + m * 16 + gid;
        const int oc1 = oc0 + 8;
        const float dm0 = g_demod[b * COUT + oc0], bs0 = bias[oc0];
        const float dm1 = g_demod[b * COUT + oc1], bs1 = bias[oc1];
        float* r0 = out + (((size_t)b * COUT + oc0) * HH + y) * WW;
        float* r1 = out + (((size_t)b * COUT + oc1) * HH + y) * WW;
        #pragma unroll
        for (int n = 0; n < 2; n++) {
            const int px = x0 + wn * 32 + n * 16 + tig * 4;
            // quads: 0 = (row gid, tileA), 1 = (row gid, tileB), 2/3 = row gid+8
            float y0A = acc[m][0][n][0] + acc[m][1][n][0] + acc[m][2][n][0];
            float y1A = acc[m][1][n][0] - acc[m][2][n][0] - acc[m][3][n][0];
            float y0B = acc[m][0][n][1] + acc[m][1][n][1] + acc[m][2][n][1];
            float y1B = acc[m][1][n][1] - acc[m][2][n][1] - acc[m][3][n][1];
            float4 v0 = make_float4(y0A * dm0 + bs0, y1A * dm0 + bs0,
                                    y0B * dm0 + bs0, y1B * dm0 + bs0);
            float y0C = acc[m][0][n][2] + acc[m][1][n][2] + acc[m][2][n][2];
            float y1C = acc[m][1][n][2] - acc[m][2][n][2] - acc[m][3][n][2];
            float y0D = acc[m][0][n][3] + acc[m][1][n][3] + acc[m][2][n][3];
            float y1D = acc[m][1][n][3] - acc[m][2][n][3] - acc[m][3][n][3];
            float4 v1 = make_float4(y0C * dm1 + bs1, y1C * dm1 + bs1,
                                    y0D * dm1 + bs1, y1D * dm1 + bs1);
            *(float4*)(r0 + px) = v0;
            *(float4*)(r1 + px) = v1;
        }
    }
}

// ---------------------------------------------------------------------------
extern "C" void kernel_launch(void* const* d_in, const int* in_sizes, int n_in,
                              void* d_out, int out_size) {
    const float* x       = (const float*)d_in[0];
    const float* w       = (const float*)d_in[1];
    const float* weight  = (const float*)d_in[2];
    const float* style_W = (const float*)d_in[3];
    const float* style_b = (const float*)d_in[4];
    const float* bias    = (const float*)d_in[5];
    float* out = (float*)d_out;

    prep1<<<192, 256>>>(w, style_W, style_b, weight);
    prep2<<<896, 256>>>(weight);

    dim3 grid(2, HH, Bq);
    conv_mma_kernel<<<grid, 512>>>(x, bias, out);
}

// round 10
// speedup vs baseline: 1.3254x; 1.3254x over previous
#include <cuda_runtime.h>
#include <cuda_fp16.h>
#include <cstdint>

#define Bq    8
#define CIN   128
#define COUT  128
#define HH    256
#define WW    256
#define SDIM  512

#define PXW   20            // words per px in a plane (16 cp + 4 pad) -> conflict-free
#define NPX   66            // 64 px + 2 halo
#define KPL   (NPX * PXW)   // 1320 words per plane

__device__ float  g_style[Bq * CIN];
__device__ float  g_demod[Bq * COUT];
__device__ float  g_W2[COUT * CIN];
__device__ __half g_wU[48 * 4096];   // t = (g*4+k)*3+s, fragment-ordered U_k (k3 negated)

#define MMA_F16(d, a, bb)                                                 \
    asm volatile("mma.sync.aligned.m16n8k16.row.col.f32.f16.f16.f32 "     \
                 "{%0,%1,%2,%3}, {%4,%5,%6,%7}, {%8,%9}, {%0,%1,%2,%3};"  \
                 : "+f"((d)[0]), "+f"((d)[1]), "+f"((d)[2]), "+f"((d)[3]) \
                 : "r"((a)[0]), "r"((a)[1]), "r"((a)[2]), "r"((a)[3]),    \
                   "r"((bb)[0]), "r"((bb)[1]))

// ---------------------------------------------------------------------------
// prep1: blocks 0..127 style GEMV (warp per (b,o)); blocks 128..191 W2
// ---------------------------------------------------------------------------
__global__ void prep1(const float* __restrict__ w,
                      const float* __restrict__ style_W,
                      const float* __restrict__ style_b,
                      const float* __restrict__ weight) {
    if (blockIdx.x < 128) {
        const int gw   = blockIdx.x * 8 + (threadIdx.x >> 5);
        const int lane = threadIdx.x & 31;
        const int b = gw >> 7, o = gw & 127;
        const float4* wv = (const float4*)(w + (size_t)b * SDIM);
        const float4* Wv = (const float4*)(style_W + (size_t)o * SDIM);
        float acc = 0.f;
        #pragma unroll
        for (int k = 0; k < 4; k++) {
            float4 a = wv[lane + k * 32], c = Wv[lane + k * 32];
            acc += a.x * c.x + a.y * c.y + a.z * c.z + a.w * c.w;
        }
        #pragma unroll
        for (int d = 16; d > 0; d >>= 1)
            acc += __shfl_xor_sync(0xffffffffu, acc, d);
        if (lane == 0) g_style[b * CIN + o] = acc + style_b[o];
    } else {
        int idx = (blockIdx.x - 128) * 256 + threadIdx.x;
        const float* p = weight + (size_t)idx * 9;
        float s = 0.f;
        #pragma unroll
        for (int t = 0; t < 9; t++) { float v = p[t]; s += v * v; }
        g_W2[idx] = s;
    }
}

// ---------------------------------------------------------------------------
// prep2: blocks 0..767 = U prepack (fragment order, proven mapping); 768..895 demod
//   t = idx>>12 in 0..47:  s = t%3 (dx), q = t/3, k = q&3 (y-transform), g = q>>2 (chunk)
//   U_k over dy taps (w0,w1,w2):  u0=w0, u1=(w0+w1+w2)/2, u2=(w0-w1+w2)/2, u3=-w2
// ---------------------------------------------------------------------------
__global__ void prep2(const float* __restrict__ weight) {
    if (blockIdx.x < 768) {
        int idx  = blockIdx.x * 256 + threadIdx.x;     // < 196608
        int h    = idx & 1;
        int j    = (idx >> 1) & 3;
        int lane = (idx >> 3) & 31;
        int mt   = (idx >> 8) & 7;
        int kk   = (idx >> 11) & 1;
        int t    = idx >> 12;                          // 0..47
        int s  = t % 3;
        int q  = t / 3;
        int k  = q & 3;
        int g  = q >> 2;
        int m  = mt * 16 + (lane >> 2) + 8 * (j & 1);
        int kl = kk * 16 + (lane & 3) * 2 + 8 * (j >> 1) + h;
        int c  = g * 32 + kl;
        const float* wp = weight + ((size_t)m * CIN + c) * 9 + s;   // + dy*3
        float w0 = wp[0], w1 = wp[3], w2 = wp[6];
        float u = (k == 0) ? w0
                : (k == 1) ? 0.5f * (w0 + w1 + w2)
                : (k == 2) ? 0.5f * (w0 - w1 + w2)
                : -w2;
        g_wU[idx] = __float2half_rn(u);
    } else {
        int gw   = (blockIdx.x - 768) * 8 + (threadIdx.x >> 5);
        int lane = threadIdx.x & 31;
        int b = gw >> 7, o = gw & 127;
        float sum = 0.f;
        #pragma unroll
        for (int j = 0; j < 4; j++) {
            int i = lane + j * 32;
            float s = g_style[b * CIN + i];
            sum += s * s * g_W2[o * CIN + i];
        }
        #pragma unroll
        for (int d = 16; d > 0; d >>= 1)
            sum += __shfl_xor_sync(0xffffffffu, sum, d);
        if (lane == 0) g_demod[b * COUT + o] = rsqrtf(sum + 1e-8f);
    }
}

// ---------------------------------------------------------------------------
// main conv: CTA = (xq, ypair, b): 128 oc x 64 px x 2 rows, y-Winograd F(2,3).
// 8 warps = 2(wm: 64oc) x 4(wn: 16px). accY0/accY1 64 regs + temp 32.
// ---------------------------------------------------------------------------
__global__ __launch_bounds__(256, 2)
void conv_mma_kernel(const float* __restrict__ x,
                     const float* __restrict__ bias,
                     float* __restrict__ out) {
    __shared__ float    styl[CIN];
    __shared__ uint32_t stage[2][4 * KPL];   // [buf][plane k][px][cp]

    const int tid  = threadIdx.x;
    const int lane = tid & 31;
    const int warp = tid >> 5;
    const int wm   = warp >> 2;      // 0..1
    const int wn   = warp & 3;       // 0..3
    const int x0   = blockIdx.x * 64;
    const int y0   = blockIdx.y * 2;
    const int b    = blockIdx.z;

    const int gid = lane >> 2;       // 0..7
    const int tig = lane & 3;        // 0..3

    if (tid < CIN) styl[tid] = g_style[b * CIN + tid];
    __syncthreads();

    float accY0[4][2][4], accY1[4][2][4], tmp[4][2][4];
    #pragma unroll
    for (int m = 0; m < 4; m++)
        #pragma unroll
        for (int n = 0; n < 2; n++)
            #pragma unroll
            for (int j = 0; j < 4; j++) { accY0[m][n][j] = 0.f; accY1[m][n][j] = 0.f; }

    // fill mapping: main spx = tid>>2 (0..63), cp = tid&3 + 4*ii; tail warp0 spx 64,65
    const int fpx = tid >> 2;
    const int fc  = tid & 3;
    const int tpx = 64 + (lane >> 4);
    const int tcp = lane & 15;

    // ---- fill: 4 x-rows -> 4 transformed planes (style-scaled, fp32 -> half2)
    auto fill = [&](uint32_t* buf) {
        const bool ok0 = y0 > 0;           // row y0-1
        const bool ok3 = y0 + 2 < HH;      // row y0+2
        auto doItem = [&](int spx, int cp) {
            const int gx = x0 - 1 + spx;
            const bool xok = (unsigned)gx < (unsigned)WW;
            const int ch = 2 * cp;
            const float sA = styl[ch], sB = styl[ch + 1];
            const float* pA = x + (((size_t)b * CIN + ch) * HH + (y0 - 1)) * WW + gx;
            const float* pB = pA + (size_t)HH * WW;
            float dA[4] = {0.f, 0.f, 0.f, 0.f}, dB[4] = {0.f, 0.f, 0.f, 0.f};
            if (xok) {
                if (ok0) { dA[0] = __ldg(pA);          dB[0] = __ldg(pB); }
                dA[1] = __ldg(pA + WW);     dB[1] = __ldg(pB + WW);
                dA[2] = __ldg(pA + 2 * WW); dB[2] = __ldg(pB + 2 * WW);
                if (ok3) { dA[3] = __ldg(pA + 3 * WW); dB[3] = __ldg(pB + 3 * WW); }
            }
            #pragma unroll
            for (int r = 0; r < 4; r++) { dA[r] *= sA; dB[r] *= sB; }
            const uint32_t base = (uint32_t)(spx * PXW + cp);
            __half2 h0 = __floats2half2_rn(dA[0] - dA[2], dB[0] - dB[2]);
            __half2 h1 = __floats2half2_rn(dA[1] + dA[2], dB[1] + dB[2]);
            __half2 h2 = __floats2half2_rn(dA[2] - dA[1], dB[2] - dB[1]);
            __half2 h3 = __floats2half2_rn(dA[1] - dA[3], dB[1] - dB[3]);
            buf[0 * KPL + base] = *(uint32_t*)&h0;
            buf[1 * KPL + base] = *(uint32_t*)&h1;
            buf[2 * KPL + base] = *(uint32_t*)&h2;
            buf[3 * KPL + base] = *(uint32_t*)&h3;
        };
        #pragma unroll
        for (int ii = 0; ii < 4; ii++) doItem(fpx, fc + 4 * ii);
        if (warp == 0) doItem(tpx, tcp);
    };

    // NOTE: fill reads channels 2cp,2cp+1 of chunk g via styl offset — bake chunk in:
    // (we re-dispatch per g below by adjusting pointers; doItem uses ch relative to chunk)
    // -> implemented via g-dependent wrappers:
    auto fillg = [&](int g, uint32_t* buf) {
        const int c0 = g * 32;
        const bool ok0 = y0 > 0;
        const bool ok3 = y0 + 2 < HH;
        auto doItem = [&](int spx, int cp) {
            const int gx = x0 - 1 + spx;
            const bool xok = (unsigned)gx < (unsigned)WW;
            const int ch = c0 + 2 * cp;
            const float sA = styl[ch], sB = styl[ch + 1];
            const float* pA = x + (((size_t)b * CIN + ch) * HH + (y0 - 1)) * WW + gx;
            const float* pB = pA + (size_t)HH * WW;
            float dA[4] = {0.f, 0.f, 0.f, 0.f}, dB[4] = {0.f, 0.f, 0.f, 0.f};
            if (xok) {
                if (ok0) { dA[0] = __ldg(pA);          dB[0] = __ldg(pB); }
                dA[1] = __ldg(pA + WW);     dB[1] = __ldg(pB + WW);
                dA[2] = __ldg(pA + 2 * WW); dB[2] = __ldg(pB + 2 * WW);
                if (ok3) { dA[3] = __ldg(pA + 3 * WW); dB[3] = __ldg(pB + 3 * WW); }
            }
            #pragma unroll
            for (int r = 0; r < 4; r++) { dA[r] *= sA; dB[r] *= sB; }
            const uint32_t base = (uint32_t)(spx * PXW + cp);
            __half2 h0 = __floats2half2_rn(dA[0] - dA[2], dB[0] - dB[2]);
            __half2 h1 = __floats2half2_rn(dA[1] + dA[2], dB[1] + dB[2]);
            __half2 h2 = __floats2half2_rn(dA[2] - dA[1], dB[2] - dB[1]);
            __half2 h3 = __floats2half2_rn(dA[1] - dA[3], dB[1] - dB[3]);
            buf[0 * KPL + base] = *(uint32_t*)&h0;
            buf[1 * KPL + base] = *(uint32_t*)&h1;
            buf[2 * KPL + base] = *(uint32_t*)&h2;
            buf[3 * KPL + base] = *(uint32_t*)&h3;
        };
        #pragma unroll
        for (int ii = 0; ii < 4; ii++) doItem(fpx, fc + 4 * ii);
        if (warp == 0) doItem(tpx, tcp);
    };
    (void)fill;

    // ---- compute plane (g,k) into given accumulator: 3 dx-steps x 2 kk x 8 MMA
    auto plane = [&](float (*acc)[2][4], const uint32_t* stg, int g, int k) {
        const uint32_t* pl = stg + k * KPL;
        #pragma unroll
        for (int s = 0; s < 3; s++) {
            const int t = (g * 4 + k) * 3 + s;
            #pragma unroll
            for (int kk = 0; kk < 2; kk++) {
                const uint4* As = ((const uint4*)g_wU) +
                                  (((size_t)(t * 2 + kk) * 8 + wm * 4) * 32 + lane);
                uint4 af[4];
                #pragma unroll
                for (int m = 0; m < 4; m++) af[m] = __ldg(As + m * 32);
                uint32_t bb[2][2];
                #pragma unroll
                for (int n = 0; n < 2; n++) {
                    const uint32_t* p = pl + (wn * 16 + n * 8 + gid + s) * PXW + kk * 8 + tig;
                    bb[n][0] = p[0];
                    bb[n][1] = p[4];
                }
                #pragma unroll
                for (int m = 0; m < 4; m++) {
                    const uint32_t* a = (const uint32_t*)&af[m];
                    MMA_F16(acc[m][0], a, bb[0]);
                    MMA_F16(acc[m][1], a, bb[1]);
                }
            }
        }
    };

    fillg(0, stage[0]);
    __syncthreads();

    #pragma unroll 1
    for (int g = 0; g < 4; g++) {
        const int cur = g & 1;
        // k=0 -> y0 directly
        plane(accY0, stage[cur], g, 0);
        if (g < 3) fillg(g + 1, stage[cur ^ 1]);
        // k=1 -> temp, fold (+y0, +y1)
        #pragma unroll
        for (int m = 0; m < 4; m++)
            #pragma unroll
            for (int n = 0; n < 2; n++)
                #pragma unroll
                for (int j = 0; j < 4; j++) tmp[m][n][j] = 0.f;
        plane(tmp, stage[cur], g, 1);
        #pragma unroll
        for (int m = 0; m < 4; m++)
            #pragma unroll
            for (int n = 0; n < 2; n++)
                #pragma unroll
                for (int j = 0; j < 4; j++) {
                    accY0[m][n][j] += tmp[m][n][j];
                    accY1[m][n][j] += tmp[m][n][j];
                }
        // k=2 -> temp, fold (+y0, -y1)
        #pragma unroll
        for (int m = 0; m < 4; m++)
            #pragma unroll
            for (int n = 0; n < 2; n++)
                #pragma unroll
                for (int j = 0; j < 4; j++) tmp[m][n][j] = 0.f;
        plane(tmp, stage[cur], g, 2);
        #pragma unroll
        for (int m = 0; m < 4; m++)
            #pragma unroll
            for (int n = 0; n < 2; n++)
                #pragma unroll
                for (int j = 0; j < 4; j++) {
                    accY0[m][n][j] += tmp[m][n][j];
                    accY1[m][n][j] -= tmp[m][n][j];
                }
        // k=3 (U negated at prepack) -> y1 directly
        plane(accY1, stage[cur], g, 3);
        __syncthreads();
    }

    // ---- epilogue: demod + bias, float2 stores, rows y0 and y0+1 ----
    #pragma unroll
    for (int m = 0; m < 4; m++) {
        const int oc0 = wm * 64 + m * 16 + gid;
        const int oc1 = oc0 + 8;
        const float dm0 = g_demod[b * COUT + oc0], bs0 = bias[oc0];
        const float dm1 = g_demod[b * COUT + oc1], bs1 = bias[oc1];
        float* p00 = out + (((size_t)b * COUT + oc0) * HH + y0) * WW;
        float* p01 = p00 + WW;
        float* p10 = out + (((size_t)b * COUT + oc1) * HH + y0) * WW;
        float* p11 = p10 + WW;
        #pragma unroll
        for (int n = 0; n < 2; n++) {
            const int px = x0 + wn * 16 + n * 8 + tig * 2;
            *(float2*)(p00 + px) = make_float2(accY0[m][n][0] * dm0 + bs0,
                                               accY0[m][n][1] * dm0 + bs0);
            *(float2*)(p01 + px) = make_float2(accY1[m][n][0] * dm0 + bs0,
                                               accY1[m][n][1] * dm0 + bs0);
            *(float2*)(p10 + px) = make_float2(accY0[m][n][2] * dm1 + bs1,
                                               accY0[m][n][3] * dm1 + bs1);
            *(float2*)(p11 + px) = make_float2(accY1[m][n][2] * dm1 + bs1,
                                               accY1[m][n][3] * dm1 + bs1);
        }
    }
}

// ---------------------------------------------------------------------------
extern "C" void kernel_launch(void* const* d_in, const int* in_sizes, int n_in,
                              void* d_out, int out_size) {
    const float* x       = (const float*)d_in[0];
    const float* w       = (const float*)d_in[1];
    const float* weight  = (const float*)d_in[2];
    const float* style_W = (const float*)d_in[3];
    const float* style_b = (const float*)d_in[4];
    const float* bias    = (const float*)d_in[5];
    float* out = (float*)d_out;

    prep1<<<192, 256>>>(w, style_W, style_b, weight);
    prep2<<<896, 256>>>(weight);

    dim3 grid(4, HH / 2, Bq);
    conv_mma_kernel<<<grid, 256>>>(x, bias, out);
}

// round 11
// speedup vs baseline: 1.3604x; 1.0264x over previous
#include <cuda_runtime.h>
#include <cuda_fp16.h>
#include <cstdint>

#define Bq    8
#define CIN   128
#define COUT  128
#define HH    256
#define WW    256
#define SDIM  512

#define PXW   20            // words per px in a plane (16 cp + 4 pad) -> conflict-free
#define NPX   66            // 64 px + 2 halo
#define KPL   (NPX * PXW)   // 1320 words per plane

__device__ float  g_style[Bq * CIN];
__device__ float  g_demod[Bq * COUT];
__device__ float  g_W2[COUT * CIN];
__device__ __half g_wU[48 * 4096];   // t=(g*4+k)*3+s, fragment-ordered U_k (k3 negated)

#define MMA_F16(d, a, bb)                                                 \
    asm volatile("mma.sync.aligned.m16n8k16.row.col.f32.f16.f16.f32 "     \
                 "{%0,%1,%2,%3}, {%4,%5,%6,%7}, {%8,%9}, {%0,%1,%2,%3};"  \
                 : "+f"((d)[0]), "+f"((d)[1]), "+f"((d)[2]), "+f"((d)[3]) \
                 : "r"((a)[0]), "r"((a)[1]), "r"((a)[2]), "r"((a)[3]),    \
                   "r"((bb)[0]), "r"((bb)[1]))

// ---------------------------------------------------------------------------
// prep1: blocks 0..127 style GEMV (warp per (b,o)); blocks 128..191 W2
// ---------------------------------------------------------------------------
__global__ void prep1(const float* __restrict__ w,
                      const float* __restrict__ style_W,
                      const float* __restrict__ style_b,
                      const float* __restrict__ weight) {
    if (blockIdx.x < 128) {
        const int gw   = blockIdx.x * 8 + (threadIdx.x >> 5);
        const int lane = threadIdx.x & 31;
        const int b = gw >> 7, o = gw & 127;
        const float4* wv = (const float4*)(w + (size_t)b * SDIM);
        const float4* Wv = (const float4*)(style_W + (size_t)o * SDIM);
        float acc = 0.f;
        #pragma unroll
        for (int k = 0; k < 4; k++) {
            float4 a = wv[lane + k * 32], c = Wv[lane + k * 32];
            acc += a.x * c.x + a.y * c.y + a.z * c.z + a.w * c.w;
        }
        #pragma unroll
        for (int d = 16; d > 0; d >>= 1)
            acc += __shfl_xor_sync(0xffffffffu, acc, d);
        if (lane == 0) g_style[b * CIN + o] = acc + style_b[o];
    } else {
        int idx = (blockIdx.x - 128) * 256 + threadIdx.x;
        const float* p = weight + (size_t)idx * 9;
        float s = 0.f;
        #pragma unroll
        for (int t = 0; t < 9; t++) { float v = p[t]; s += v * v; }
        g_W2[idx] = s;
    }
}

// ---------------------------------------------------------------------------
// prep2: blocks 0..767 = U prepack (proven R10 mapping); 768..895 demod
// ---------------------------------------------------------------------------
__global__ void prep2(const float* __restrict__ weight) {
    if (blockIdx.x < 768) {
        int idx  = blockIdx.x * 256 + threadIdx.x;     // < 196608
        int h    = idx & 1;
        int j    = (idx >> 1) & 3;
        int lane = (idx >> 3) & 31;
        int mt   = (idx >> 8) & 7;
        int kk   = (idx >> 11) & 1;
        int t    = idx >> 12;                          // 0..47
        int s  = t % 3;
        int q  = t / 3;
        int k  = q & 3;
        int g  = q >> 2;
        int m  = mt * 16 + (lane >> 2) + 8 * (j & 1);
        int kl = kk * 16 + (lane & 3) * 2 + 8 * (j >> 1) + h;
        int c  = g * 32 + kl;
        const float* wp = weight + ((size_t)m * CIN + c) * 9 + s;
        float w0 = wp[0], w1 = wp[3], w2 = wp[6];
        float u = (k == 0) ? w0
                : (k == 1) ? 0.5f * (w0 + w1 + w2)
                : (k == 2) ? 0.5f * (w0 - w1 + w2)
                : -w2;
        g_wU[idx] = __float2half_rn(u);
    } else {
        int gw   = (blockIdx.x - 768) * 8 + (threadIdx.x >> 5);
        int lane = threadIdx.x & 31;
        int b = gw >> 7, o = gw & 127;
        float sum = 0.f;
        #pragma unroll
        for (int j = 0; j < 4; j++) {
            int i = lane + j * 32;
            float s = g_style[b * CIN + i];
            sum += s * s * g_W2[o * CIN + i];
        }
        #pragma unroll
        for (int d = 16; d > 0; d >>= 1)
            sum += __shfl_xor_sync(0xffffffffu, sum, d);
        if (lane == 0) g_demod[b * COUT + o] = rsqrtf(sum + 1e-8f);
    }
}

// ---------------------------------------------------------------------------
// main conv: CTA = (xq, ypair, b): 128 oc x 64 px x 2 rows, y-Winograd F(2,3).
// 8 warps = 2(wm: 64oc) x 4(wn: 16px). Spill-free schedule:
//   accY0 32 + accY1 32 + tmp 16 + on-demand frags ~8 + idx ~15 ≈ 105 regs.
// ---------------------------------------------------------------------------
__global__ __launch_bounds__(256, 2)
void conv_mma_kernel(const float* __restrict__ x,
                     const float* __restrict__ bias,
                     float* __restrict__ out) {
    __shared__ float    styl[CIN];
    __shared__ uint32_t stage[2][4 * KPL];   // [buf][plane k][px][cp]

    const int tid  = threadIdx.x;
    const int lane = tid & 31;
    const int warp = tid >> 5;
    const int wm   = warp >> 2;      // 0..1
    const int wn   = warp & 3;       // 0..3
    const int x0   = blockIdx.x * 64;
    const int y0   = blockIdx.y * 2;
    const int b    = blockIdx.z;

    const int gid = lane >> 2;       // 0..7
    const int tig = lane & 3;        // 0..3

    if (tid < CIN) styl[tid] = g_style[b * CIN + tid];
    __syncthreads();

    float accY0[4][2][4], accY1[4][2][4];
    #pragma unroll
    for (int m = 0; m < 4; m++)
        #pragma unroll
        for (int n = 0; n < 2; n++)
            #pragma unroll
            for (int j = 0; j < 4; j++) { accY0[m][n][j] = 0.f; accY1[m][n][j] = 0.f; }

    // fill mapping
    const int fpx = tid >> 2;
    const int fc  = tid & 3;
    const int tpx = 64 + (lane >> 4);
    const int tcp = lane & 15;

    // ---- fill: 4 x-rows -> 4 transformed planes (style-scaled fp32 -> half2)
    auto fillg = [&](int g, uint32_t* buf) {
        const int c0 = g * 32;
        const bool ok0 = y0 > 0;
        const bool ok3 = y0 + 2 < HH;
        auto doItem = [&](int spx, int cp) {
            const int gx = x0 - 1 + spx;
            const bool xok = (unsigned)gx < (unsigned)WW;
            const int ch = c0 + 2 * cp;
            const float sA = styl[ch], sB = styl[ch + 1];
            const float* pA = x + (((size_t)b * CIN + ch) * HH + (y0 - 1)) * WW + gx;
            const float* pB = pA + (size_t)HH * WW;
            float dA[4] = {0.f, 0.f, 0.f, 0.f}, dB[4] = {0.f, 0.f, 0.f, 0.f};
            if (xok) {
                if (ok0) { dA[0] = __ldg(pA);          dB[0] = __ldg(pB); }
                dA[1] = __ldg(pA + WW);     dB[1] = __ldg(pB + WW);
                dA[2] = __ldg(pA + 2 * WW); dB[2] = __ldg(pB + 2 * WW);
                if (ok3) { dA[3] = __ldg(pA + 3 * WW); dB[3] = __ldg(pB + 3 * WW); }
            }
            #pragma unroll
            for (int r = 0; r < 4; r++) { dA[r] *= sA; dB[r] *= sB; }
            const uint32_t base = (uint32_t)(spx * PXW + cp);
            __half2 h0 = __floats2half2_rn(dA[0] - dA[2], dB[0] - dB[2]);
            __half2 h1 = __floats2half2_rn(dA[1] + dA[2], dB[1] + dB[2]);
            __half2 h2 = __floats2half2_rn(dA[2] - dA[1], dB[2] - dB[1]);
            __half2 h3 = __floats2half2_rn(dA[1] - dA[3], dB[1] - dB[3]);
            buf[0 * KPL + base] = *(uint32_t*)&h0;
            buf[1 * KPL + base] = *(uint32_t*)&h1;
            buf[2 * KPL + base] = *(uint32_t*)&h2;
            buf[3 * KPL + base] = *(uint32_t*)&h3;
        };
        #pragma unroll
        for (int ii = 0; ii < 4; ii++) doItem(fpx, fc + 4 * ii);
        if (warp == 0) doItem(tpx, tcp);
    };

    // ---- full plane (k=0 or 3) into acc: on-demand A-frags ----
    auto plane_full = [&](float (*acc)[2][4], const uint32_t* stg, int g, int k) {
        const uint32_t* pl = stg + k * KPL;
        #pragma unroll
        for (int s = 0; s < 3; s++) {
            const int t = (g * 4 + k) * 3 + s;
            #pragma unroll
            for (int kk = 0; kk < 2; kk++) {
                uint32_t bb[2][2];
                #pragma unroll
                for (int n = 0; n < 2; n++) {
                    const uint32_t* p = pl + (wn * 16 + n * 8 + gid + s) * PXW + kk * 8 + tig;
                    bb[n][0] = p[0];
                    bb[n][1] = p[4];
                }
                const uint4* As = ((const uint4*)g_wU) +
                                  (((size_t)(t * 2 + kk) * 8 + wm * 4) * 32 + lane);
                #pragma unroll
                for (int m = 0; m < 4; m++) {
                    uint4 a = __ldg(As + m * 32);
                    MMA_F16(acc[m][0], (const uint32_t*)&a, bb[0]);
                    MMA_F16(acc[m][1], (const uint32_t*)&a, bb[1]);
                }
            }
        }
    };

    // ---- middle plane (k=1 or 2), per-n with 16-reg tmp, fold into both accs
    auto plane_fold = [&](const uint32_t* stg, int g, int k, float sgn) {
        const uint32_t* pl = stg + k * KPL;
        #pragma unroll
        for (int n = 0; n < 2; n++) {
            float tmp[4][4];
            #pragma unroll
            for (int m = 0; m < 4; m++)
                #pragma unroll
                for (int j = 0; j < 4; j++) tmp[m][j] = 0.f;
            #pragma unroll
            for (int s = 0; s < 3; s++) {
                const int t = (g * 4 + k) * 3 + s;
                #pragma unroll
                for (int kk = 0; kk < 2; kk++) {
                    uint32_t bb[2];
                    const uint32_t* p = pl + (wn * 16 + n * 8 + gid + s) * PXW + kk * 8 + tig;
                    bb[0] = p[0];
                    bb[1] = p[4];
                    const uint4* As = ((const uint4*)g_wU) +
                                      (((size_t)(t * 2 + kk) * 8 + wm * 4) * 32 + lane);
                    #pragma unroll
                    for (int m = 0; m < 4; m++) {
                        uint4 a = __ldg(As + m * 32);
                        MMA_F16(tmp[m], (const uint32_t*)&a, bb);
                    }
                }
            }
            #pragma unroll
            for (int m = 0; m < 4; m++)
                #pragma unroll
                for (int j = 0; j < 4; j++) {
                    accY0[m][n][j] += tmp[m][j];
                    accY1[m][n][j] += sgn * tmp[m][j];
                }
        }
    };

    fillg(0, stage[0]);
    __syncthreads();

    #pragma unroll 1
    for (int g = 0; g < 4; g++) {
        const int cur = g & 1;
        plane_full(accY0, stage[cur], g, 0);
        if (g < 3) fillg(g + 1, stage[cur ^ 1]);   // LDG covered by remaining planes
        plane_full(accY1, stage[cur], g, 3);       // U(k3) pre-negated
        plane_fold(stage[cur], g, 1, 1.f);
        plane_fold(stage[cur], g, 2, -1.f);
        __syncthreads();
    }

    // ---- epilogue: demod + bias, float2 stores, rows y0 and y0+1 ----
    #pragma unroll
    for (int m = 0; m < 4; m++) {
        const int oc0 = wm * 64 + m * 16 + gid;
        const int oc1 = oc0 + 8;
        const float dm0 = g_demod[b * COUT + oc0], bs0 = bias[oc0];
        const float dm1 = g_demod[b * COUT + oc1], bs1 = bias[oc1];
        float* p00 = out + (((size_t)b * COUT + oc0) * HH + y0) * WW;
        float* p01 = p00 + WW;
        float* p10 = out + (((size_t)b * COUT + oc1) * HH + y0) * WW;
        float* p11 = p10 + WW;
        #pragma unroll
        for (int n = 0; n < 2; n++) {
            const int px = x0 + wn * 16 + n * 8 + tig * 2;
            *(float2*)(p00 + px) = make_float2(accY0[m][n][0] * dm0 + bs0,
                                               accY0[m][n][1] * dm0 + bs0);
            *(float2*)(p01 + px) = make_float2(accY1[m][n][0] * dm0 + bs0,
                                               accY1[m][n][1] * dm0 + bs0);
            *(float2*)(p10 + px) = make_float2(accY0[m][n][2] * dm1 + bs1,
                                               accY0[m][n][3] * dm1 + bs1);
            *(float2*)(p11 + px) = make_float2(accY1[m][n][2] * dm1 + bs1,
                                               accY1[m][n][3] * dm1 + bs1);
        }
    }
}

// ---------------------------------------------------------------------------
extern "C" void kernel_launch(void* const* d_in, const int* in_sizes, int n_in,
                              void* d_out, int out_size) {
    const float* x       = (const float*)d_in[0];
    const float* w       = (const float*)d_in[1];
    const float* weight  = (const float*)d_in[2];
    const float* style_W = (const float*)d_in[3];
    const float* style_b = (const float*)d_in[4];
    const float* bias    = (const float*)d_in[5];
    float* out = (float*)d_out;

    prep1<<<192, 256>>>(w, style_W, style_b, weight);
    prep2<<<896, 256>>>(weight);

    dim3 grid(4, HH / 2, Bq);
    conv_mma_kernel<<<grid, 256>>>(x, bias, out);
}